// round 15
// baseline (speedup 1.0000x reference)
#include <cuda_runtime.h>
#include <math.h>

// ---------------- problem constants ----------------
#define BN    4096
#define NN    12288          // 3*BN
#define DIM   128
#define MS    10
#define MTS   12             // padded mail-row stride (16B aligned)
#define DMSG  384            // 2*DIM + DIM_EDGE
#define DKIN  484            // DMSG + DTIME
#define DTIME 100
#define EE    81920
#define UU    50000
#define EPSV  1e-5f
#define G     4              // nodes per block in k_node

// output layout (flattened tuple, in reference return order)
#define OFF_POS   ((size_t)NN * DIM)                 // 1,572,864
#define OFF_NEG   (OFF_POS + BN)                     // 1,576,960
#define OFF_MAIL  (OFF_NEG + BN)                     // 1,581,056
#define OFF_TS    (OFF_MAIL + (size_t)UU * DMSG)     // 20,781,056

// device scratch (no allocations allowed)
__device__ float g_cnt[UU];
__device__ float g_wkv[DKIN * 256];  // interleaved (wk[j][c], wv[j][c])

// ---------------- helpers ----------------
typedef unsigned long long ull;

static __device__ __forceinline__ ull pack2(float x) {
    ull r;
    unsigned u = __float_as_uint(x);
    asm("mov.b64 %0, {%1, %1};" : "=l"(r) : "r"(u));
    return r;
}
static __device__ __forceinline__ ull ffma2(ull a, ull b, ull c) {
    ull d;
    asm("fma.rn.f32x2 %0, %1, %2, %3;" : "=l"(d) : "l"(a), "l"(b), "l"(c));
    return d;
}
static __device__ __forceinline__ float lo32(ull u) {
    return __uint_as_float((unsigned)u);
}
static __device__ __forceinline__ float hi32(ull u) {
    return __uint_as_float((unsigned)(u >> 32));
}
static __device__ __forceinline__ float warpsum(float v) {
    #pragma unroll
    for (int o = 16; o; o >>= 1) v += __shfl_down_sync(0xffffffffu, v, o);
    return v;
}

// shared layout for k_node (floats): per node-group of G
//   mailT  : G*484*12   (transposed, padded: [j][m], 48B rows)
//   mem_sm : G*128
//   nrm_sm : G*128
//   attn_p : G*4*10     (per-warp partials)
//   attn_w : G*2*10     (softmax weights per head)
//   red    : G*4*2      (layernorm partials)
#define SM_MAILT   0
#define SM_MEM     (G * (DKIN * MTS))
#define SM_NRM     (SM_MEM + G * 128)
#define SM_ATTNP   (SM_NRM + G * 128)
#define SM_ATTNW   (SM_ATTNP + G * 40)
#define SM_RED     (SM_ATTNW + G * 20)
#define SM_FLOATS  (SM_RED + G * 8)
#define SM_BYTES   (SM_FLOATS * 4)

// ---------------- kernel 0: interleave wk/wv weights ----------------
__global__ void k_prep(const float* __restrict__ wk_w, const float* __restrict__ wv_w) {
    int idx = blockIdx.x * blockDim.x + threadIdx.x;   // DKIN*DIM threads
    if (idx < DKIN * DIM) {
        int j = idx >> 7, c = idx & 127;
        g_wkv[j * 256 + 2 * c]     = wk_w[idx];
        g_wkv[j * 256 + 2 * c + 1] = wv_w[idx];
    }
}

// ---------------- kernel 1: per-node attention + LN + MLP ----------------
__global__ __launch_bounds__(512, 2)
void k_node(const int* __restrict__ nodes, const float* __restrict__ times,
            const float* __restrict__ mem_table, const float* __restrict__ mail_table,
            const float* __restrict__ mail_time,
            const float* __restrict__ wq_w, const float* __restrict__ wq_b,
            const float* __restrict__ wk_b, const float* __restrict__ wv_b,
            const float* __restrict__ te_w, const float* __restrict__ te_b,
            const float* __restrict__ mlp_w, const float* __restrict__ mlp_b,
            const float* __restrict__ ln_g, const float* __restrict__ ln_b,
            float* __restrict__ out) {
    extern __shared__ float sm[];
    float* mailT  = sm + SM_MAILT;
    float* mem_sm = sm + SM_MEM;
    float* nrm_sm = sm + SM_NRM;
    float* attn_p = sm + SM_ATTNP;
    float* attn_w = sm + SM_ATTNW;
    float* red    = sm + SM_RED;

    const int tid    = threadIdx.x;
    const int wg     = tid >> 7;       // node index within block (0..3)
    const int c      = tid & 127;      // column (0..127)
    const int lane   = tid & 31;
    const int warpIn = (tid >> 5) & 3; // warp within node group

    const int node_i = blockIdx.x * G + wg;
    const int node   = nodes[node_i];
    const float t_now = times[node_i];

    // mem row: register + shared (for Q gemm)
    const float memv = mem_table[(size_t)node * DIM + c];
    mem_sm[wg * 128 + c] = memv;

    // build transposed mail matrix mailT[j][m] (row stride MTS floats)
    const float* mrow_base = mail_table + (size_t)node * MS * DMSG;
    float* mt = mailT + wg * (DKIN * MTS);
    #pragma unroll
    for (int m = 0; m < MS; m++) {
        #pragma unroll
        for (int r = 0; r < 3; r++) {
            int j = c + r * 128;
            mt[j * MTS + m] = mrow_base[m * DMSG + j];
        }
        float dtv = t_now - mail_time[node * MS + m];
        if (c < DTIME) {
            mt[(DMSG + c) * MTS + m] = cosf(dtv * te_w[c] + te_b[c]);
        }
    }
    __syncthreads();

    // Q column c
    float q = wq_b[c];
    {
        const float* msrow = mem_sm + wg * 128;
        #pragma unroll 4
        for (int j = 0; j < DIM; j++) q = fmaf(msrow[j], wq_w[j * DIM + c], q);
    }

    // K/V projection: 10 mail rows at once, packed f32x2 across m-pairs
    ull Kacc[5] = {0, 0, 0, 0, 0};
    ull Vacc[5] = {0, 0, 0, 0, 0};
    {
        const float2* wkv = (const float2*)g_wkv;
        #pragma unroll 2
        for (int j = 0; j < DKIN; j++) {
            float2 w2 = wkv[j * 128 + c];
            ull wk2 = pack2(w2.x);
            ull wv2 = pack2(w2.y);
            const float* row = mt + j * MTS;
            longlong2 A = *(const longlong2*)(row);       // m0..3
            longlong2 Bq = *(const longlong2*)(row + 4);  // m4..7
            ull C = *(const ull*)(row + 8);               // m8..9
            ull mm0 = (ull)A.x,  mm1 = (ull)A.y;
            ull mm2 = (ull)Bq.x, mm3 = (ull)Bq.y;
            Kacc[0] = ffma2(mm0, wk2, Kacc[0]);  Vacc[0] = ffma2(mm0, wv2, Vacc[0]);
            Kacc[1] = ffma2(mm1, wk2, Kacc[1]);  Vacc[1] = ffma2(mm1, wv2, Vacc[1]);
            Kacc[2] = ffma2(mm2, wk2, Kacc[2]);  Vacc[2] = ffma2(mm2, wv2, Vacc[2]);
            Kacc[3] = ffma2(mm3, wk2, Kacc[3]);  Vacc[3] = ffma2(mm3, wv2, Vacc[3]);
            Kacc[4] = ffma2(C,   wk2, Kacc[4]);  Vacc[4] = ffma2(C,   wv2, Vacc[4]);
        }
    }

    // attention logits: per-warp partial dot(Q, K) within head
    const float wkb = wk_b[c];
    const float wvb = wv_b[c];
    {
        float* ap = attn_p + wg * 40 + warpIn * 10;
        #pragma unroll
        for (int m = 0; m < MS; m++) {
            float Kv = ((m & 1) ? hi32(Kacc[m >> 1]) : lo32(Kacc[m >> 1])) + wkb;
            float s = warpsum(q * Kv);
            if (lane == 0) ap[m] = s;
        }
    }
    __syncthreads();

    // leaky-relu + softmax over m (one thread per head)
    if ((c & 63) == 0) {
        int h = c >> 6;
        const float* p0 = attn_p + wg * 40 + (2 * h) * 10;
        const float* p1 = p0 + 10;
        float a[MS];
        float mx = -1e30f;
        #pragma unroll
        for (int m = 0; m < MS; m++) {
            float x = p0[m] + p1[m];
            x = x > 0.f ? x : 0.2f * x;
            a[m] = x;
            mx = fmaxf(mx, x);
        }
        float se = 0.f;
        #pragma unroll
        for (int m = 0; m < MS; m++) { a[m] = expf(a[m] - mx); se += a[m]; }
        float inv = 1.f / se;
        float* awp = attn_w + wg * 20 + h * 10;
        #pragma unroll
        for (int m = 0; m < MS; m++) awp[m] = a[m] * inv;
    }
    __syncthreads();

    // weighted V + residual
    float o = memv;
    {
        const float* awp = attn_w + wg * 20 + (c >> 6) * 10;
        #pragma unroll
        for (int m = 0; m < MS; m++) {
            float Vv = ((m & 1) ? hi32(Vacc[m >> 1]) : lo32(Vacc[m >> 1])) + wvb;
            o = fmaf(awp[m], Vv, o);
        }
    }

    // layernorm across 128 (4 warps per node)
    {
        float s1 = warpsum(o);
        float s2 = warpsum(o * o);
        if (lane == 0) {
            red[wg * 8 + warpIn * 2]     = s1;
            red[wg * 8 + warpIn * 2 + 1] = s2;
        }
    }
    __syncthreads();
    {
        const float* rr = red + wg * 8;
        float mu  = (rr[0] + rr[2] + rr[4] + rr[6]) * (1.f / 128.f);
        float ms2 = (rr[1] + rr[3] + rr[5] + rr[7]) * (1.f / 128.f);
        float var = ms2 - mu * mu;
        float nv = (o - mu) * rsqrtf(var + EPSV) * ln_g[c] + ln_b[c];
        nrm_sm[wg * 128 + c] = nv;
    }
    __syncthreads();

    // MLP + relu -> mem_out
    {
        float acc = mlp_b[c];
        const float* nr = nrm_sm + wg * 128;
        #pragma unroll 4
        for (int j = 0; j < DIM; j++) acc = fmaf(nr[j], mlp_w[j * DIM + c], acc);
        out[(size_t)node_i * DIM + c] = fmaxf(acc, 0.f);
    }
}

// ---------------- kernel 2: link prediction heads ----------------
__global__ __launch_bounds__(128)
void k_link(const float* __restrict__ MO,
            const float* __restrict__ src_w, const float* __restrict__ src_b,
            const float* __restrict__ dst_w, const float* __restrict__ dst_b,
            const float* __restrict__ out_w, const float* __restrict__ out_b,
            float* __restrict__ pos, float* __restrict__ neg) {
    __shared__ float ssrc[128], sdst[128], sneg[128];
    __shared__ float red[8];
    const int i = blockIdx.x;
    const int c = threadIdx.x;
    const int lane = c & 31;
    const int w = c >> 5;

    ssrc[c] = MO[(size_t)i * 128 + c];
    sdst[c] = MO[(size_t)(BN + i) * 128 + c];
    sneg[c] = MO[(size_t)(2 * BN + i) * 128 + c];
    __syncthreads();

    float h = src_b[c], d = dst_b[c], n = dst_b[c];
    #pragma unroll 4
    for (int j = 0; j < 128; j++) {
        h = fmaf(ssrc[j], src_w[j * 128 + c], h);
        d = fmaf(sdst[j], dst_w[j * 128 + c], d);
        n = fmaf(sneg[j], dst_w[j * 128 + c], n);
    }
    float ow = out_w[c];
    float p = fmaxf(h + d, 0.f) * ow;
    float qn = fmaxf(h + n, 0.f) * ow;
    p = warpsum(p);
    qn = warpsum(qn);
    if (lane == 0) { red[w] = p; red[4 + w] = qn; }
    __syncthreads();
    if (c == 0) {
        float ob = out_b[0];
        pos[i] = red[0] + red[1] + red[2] + red[3] + ob;
        neg[i] = red[4] + red[5] + red[6] + red[7] + ob;
    }
}

// ---------------- kernel 3a: zero accumulators ----------------
__global__ void k_zero(float* __restrict__ out) {
    size_t i = (size_t)blockIdx.x * blockDim.x + threadIdx.x;
    const size_t MAILN = (size_t)UU * DMSG;
    if (i < MAILN) {
        out[OFF_MAIL + i] = 0.f;
    } else if (i < MAILN + UU) {
        out[OFF_TS + (i - MAILN)] = 0.f;
    } else if (i < MAILN + 2 * UU) {
        g_cnt[i - MAILN - UU] = 0.f;
    }
}

// ---------------- kernel 3b: segment scatter-add ----------------
__global__ __launch_bounds__(384)
void k_scatter(const float* __restrict__ MO, const float* __restrict__ efeat,
               const float* __restrict__ times,
               const int* __restrict__ dstindex, const int* __restrict__ src_seg,
               float* __restrict__ mail, float* __restrict__ ts) {
    const int e = blockIdx.x;
    const int c = threadIdx.x;   // 0..383
    const int r = dstindex[e];
    const int s = src_seg[e];
    float v;
    if (c < 128) {
        v = MO[(size_t)r * 128 + c];
    } else if (c < 256) {
        int r2 = (r < BN) ? (r + BN) : (r - BN);
        v = MO[(size_t)r2 * 128 + (c - 128)];
    } else {
        int rb = (r < BN) ? r : (r - BN);
        v = efeat[(size_t)rb * 128 + (c - 256)];
    }
    atomicAdd(mail + (size_t)s * DMSG + c, v);
    if (c == 0) {
        atomicAdd(&g_cnt[s], 1.0f);
        atomicAdd(ts + s, times[r]);
    }
}

// ---------------- kernel 3c: divide by counts ----------------
__global__ void k_scale(float* __restrict__ mail, float* __restrict__ ts) {
    size_t i = (size_t)blockIdx.x * blockDim.x + threadIdx.x;
    if (i < (size_t)UU * DMSG) {
        float d = fmaxf(g_cnt[i / DMSG], 1.f);
        mail[i] = mail[i] / d;
    }
    if (i < UU) {
        ts[i] = ts[i] / fmaxf(g_cnt[i], 1.f);
    }
}

// ---------------- launch ----------------
extern "C" void kernel_launch(void* const* d_in, const int* in_sizes, int n_in,
                              void* d_out, int out_size) {
    const int*   nodes      = (const int*)  d_in[0];
    const float* times      = (const float*)d_in[1];
    const float* mem_table  = (const float*)d_in[2];
    const float* mail_table = (const float*)d_in[3];
    const float* mail_time  = (const float*)d_in[4];
    const float* efeat      = (const float*)d_in[5];
    const float* wq_w = (const float*)d_in[6];
    const float* wq_b = (const float*)d_in[7];
    const float* wk_w = (const float*)d_in[8];
    const float* wk_b = (const float*)d_in[9];
    const float* wv_w = (const float*)d_in[10];
    const float* wv_b = (const float*)d_in[11];
    const float* mlp_w = (const float*)d_in[12];
    const float* mlp_b = (const float*)d_in[13];
    const float* ln_g  = (const float*)d_in[14];
    const float* ln_b  = (const float*)d_in[15];
    const float* te_w  = (const float*)d_in[16];
    const float* te_b  = (const float*)d_in[17];
    const float* src_w = (const float*)d_in[18];
    const float* src_b = (const float*)d_in[19];
    const float* dst_w = (const float*)d_in[20];
    const float* dst_b = (const float*)d_in[21];
    const float* out_w = (const float*)d_in[22];
    const float* out_b = (const float*)d_in[23];
    const int* dstindex = (const int*)d_in[24];
    const int* src_seg  = (const int*)d_in[25];

    float* out = (float*)d_out;

    cudaFuncSetAttribute(k_node, cudaFuncAttributeMaxDynamicSharedMemorySize, SM_BYTES);

    // 0) interleave K/V weights into scratch
    k_prep<<<(DKIN * DIM + 127) / 128, 128>>>(wk_w, wv_w);

    // 1) per-node attention + LN + MLP -> mem_out
    k_node<<<NN / G, 512, SM_BYTES>>>(
        nodes, times, mem_table, mail_table, mail_time,
        wq_w, wq_b, wk_b, wv_b, te_w, te_b,
        mlp_w, mlp_b, ln_g, ln_b, out);

    // 2) link prediction heads -> pos, neg
    k_link<<<BN, 128>>>(out, src_w, src_b, dst_w, dst_b, out_w, out_b,
                        out + OFF_POS, out + OFF_NEG);

    // 3) segment mean aggregation -> mail_agg, ts_agg
    {
        const size_t zeroN = (size_t)UU * DMSG + 2 * (size_t)UU;
        k_zero<<<(unsigned)((zeroN + 255) / 256), 256>>>(out);
        k_scatter<<<EE, 384>>>(out, efeat, times, dstindex, src_seg,
                               out + OFF_MAIL, out + OFF_TS);
        k_scale<<<(unsigned)(((size_t)UU * DMSG + 255) / 256), 256>>>(
            out + OFF_MAIL, out + OFF_TS);
    }
}

// round 17
// speedup vs baseline: 1.0253x; 1.0253x over previous
#include <cuda_runtime.h>
#include <math.h>

// ---------------- problem constants ----------------
#define BN    4096
#define NN    12288          // 3*BN
#define DIM   128
#define MS    10
#define MTS   12             // padded mail-row stride (16B aligned)
#define DMSG  384            // 2*DIM + DIM_EDGE
#define DKIN  484            // DMSG + DTIME
#define DTIME 100
#define EE    81920
#define UU    50000
#define EPSV  1e-5f
#define G     4              // nodes per block in k_node

#define MAIL4 ((UU * DMSG) / 4)    // 4,800,000 float4s in mail_agg
#define TS4   (UU / 4)             // 12,500 float4s in ts_agg / cnt

// output layout (flattened tuple, in reference return order)
#define OFF_POS   ((size_t)NN * DIM)                 // 1,572,864
#define OFF_NEG   (OFF_POS + BN)                     // 1,576,960
#define OFF_MAIL  (OFF_NEG + BN)                     // 1,581,056 (16B-aligned)
#define OFF_TS    (OFF_MAIL + (size_t)UU * DMSG)     // 20,781,056 (16B-aligned)

// device scratch (no allocations allowed)
__device__ __align__(16) float g_cnt[UU];
__device__ float g_wkv[DKIN * 256];  // interleaved (wk[j][c], wv[j][c])

// ---------------- helpers ----------------
typedef unsigned long long ull;

static __device__ __forceinline__ ull pack2(float x) {
    ull r;
    unsigned u = __float_as_uint(x);
    asm("mov.b64 %0, {%1, %1};" : "=l"(r) : "r"(u));
    return r;
}
static __device__ __forceinline__ ull ffma2(ull a, ull b, ull c) {
    ull d;
    asm("fma.rn.f32x2 %0, %1, %2, %3;" : "=l"(d) : "l"(a), "l"(b), "l"(c));
    return d;
}
static __device__ __forceinline__ float lo32(ull u) {
    return __uint_as_float((unsigned)u);
}
static __device__ __forceinline__ float hi32(ull u) {
    return __uint_as_float((unsigned)(u >> 32));
}
static __device__ __forceinline__ float warpsum(float v) {
    #pragma unroll
    for (int o = 16; o; o >>= 1) v += __shfl_down_sync(0xffffffffu, v, o);
    return v;
}

// shared layout for k_node (floats): per node-group of G
#define SM_MAILT   0
#define SM_MEM     (G * (DKIN * MTS))
#define SM_NRM     (SM_MEM + G * 128)
#define SM_ATTNP   (SM_NRM + G * 128)
#define SM_ATTNW   (SM_ATTNP + G * 40)
#define SM_RED     (SM_ATTNW + G * 20)
#define SM_FLOATS  (SM_RED + G * 8)
#define SM_BYTES   (SM_FLOATS * 4)

// ---------------- kernel 0: fused weight interleave + vectorized zero ----------------
__global__ void k_init(const float* __restrict__ wk_w, const float* __restrict__ wv_w,
                       float* __restrict__ out) {
    unsigned idx = blockIdx.x * blockDim.x + threadIdx.x;
    if (idx < DKIN * DIM) {
        int j = idx >> 7, c = idx & 127;
        g_wkv[j * 256 + 2 * c]     = wk_w[idx];
        g_wkv[j * 256 + 2 * c + 1] = wv_w[idx];
    }
    float4 z = make_float4(0.f, 0.f, 0.f, 0.f);
    if (idx < MAIL4) {
        reinterpret_cast<float4*>(out + OFF_MAIL)[idx] = z;
    } else if (idx < MAIL4 + TS4) {
        reinterpret_cast<float4*>(out + OFF_TS)[idx - MAIL4] = z;
    } else if (idx < MAIL4 + 2 * TS4) {
        reinterpret_cast<float4*>(g_cnt)[idx - MAIL4 - TS4] = z;
    }
}

// ---------------- kernel 1: per-node attention + LN + MLP ----------------
__global__ __launch_bounds__(512, 2)
void k_node(const int* __restrict__ nodes, const float* __restrict__ times,
            const float* __restrict__ mem_table, const float* __restrict__ mail_table,
            const float* __restrict__ mail_time,
            const float* __restrict__ wq_w, const float* __restrict__ wq_b,
            const float* __restrict__ wk_b, const float* __restrict__ wv_b,
            const float* __restrict__ te_w, const float* __restrict__ te_b,
            const float* __restrict__ mlp_w, const float* __restrict__ mlp_b,
            const float* __restrict__ ln_g, const float* __restrict__ ln_b,
            float* __restrict__ out) {
    extern __shared__ float sm[];
    float* mailT  = sm + SM_MAILT;
    float* mem_sm = sm + SM_MEM;
    float* nrm_sm = sm + SM_NRM;
    float* attn_p = sm + SM_ATTNP;
    float* attn_w = sm + SM_ATTNW;
    float* red    = sm + SM_RED;

    const int tid    = threadIdx.x;
    const int wg     = tid >> 7;       // node index within block (0..3)
    const int c      = tid & 127;      // column (0..127)
    const int lane   = tid & 31;
    const int warpIn = (tid >> 5) & 3; // warp within node group

    const int node_i = blockIdx.x * G + wg;
    const int node   = nodes[node_i];
    const float t_now = times[node_i];

    // mem row: register + shared (for Q gemm)
    const float memv = mem_table[(size_t)node * DIM + c];
    mem_sm[wg * 128 + c] = memv;

    // build transposed mail matrix mailT[j][m] (row stride MTS floats)
    const float* mrow_base = mail_table + (size_t)node * MS * DMSG;
    float* mt = mailT + wg * (DKIN * MTS);
    #pragma unroll
    for (int m = 0; m < MS; m++) {
        #pragma unroll
        for (int r = 0; r < 3; r++) {
            int j = c + r * 128;
            mt[j * MTS + m] = mrow_base[m * DMSG + j];
        }
        float dtv = t_now - mail_time[node * MS + m];
        if (c < DTIME) {
            mt[(DMSG + c) * MTS + m] = cosf(dtv * te_w[c] + te_b[c]);
        }
    }
    __syncthreads();

    // Q column c
    float q = wq_b[c];
    {
        const float* msrow = mem_sm + wg * 128;
        #pragma unroll 4
        for (int j = 0; j < DIM; j++) q = fmaf(msrow[j], wq_w[j * DIM + c], q);
    }

    // K/V projection: 10 mail rows at once, packed f32x2 across m-pairs
    ull Kacc[5] = {0, 0, 0, 0, 0};
    ull Vacc[5] = {0, 0, 0, 0, 0};
    {
        const float2* wkv = (const float2*)g_wkv;
        #pragma unroll 2
        for (int j = 0; j < DKIN; j++) {
            float2 w2 = wkv[j * 128 + c];
            ull wk2 = pack2(w2.x);
            ull wv2 = pack2(w2.y);
            const float* row = mt + j * MTS;
            longlong2 A = *(const longlong2*)(row);       // m0..3
            longlong2 Bq = *(const longlong2*)(row + 4);  // m4..7
            ull C = *(const ull*)(row + 8);               // m8..9
            ull mm0 = (ull)A.x,  mm1 = (ull)A.y;
            ull mm2 = (ull)Bq.x, mm3 = (ull)Bq.y;
            Kacc[0] = ffma2(mm0, wk2, Kacc[0]);  Vacc[0] = ffma2(mm0, wv2, Vacc[0]);
            Kacc[1] = ffma2(mm1, wk2, Kacc[1]);  Vacc[1] = ffma2(mm1, wv2, Vacc[1]);
            Kacc[2] = ffma2(mm2, wk2, Kacc[2]);  Vacc[2] = ffma2(mm2, wv2, Vacc[2]);
            Kacc[3] = ffma2(mm3, wk2, Kacc[3]);  Vacc[3] = ffma2(mm3, wv2, Vacc[3]);
            Kacc[4] = ffma2(C,   wk2, Kacc[4]);  Vacc[4] = ffma2(C,   wv2, Vacc[4]);
        }
    }

    // attention logits: per-warp partial dot(Q, K) within head
    const float wkb = wk_b[c];
    const float wvb = wv_b[c];
    {
        float* ap = attn_p + wg * 40 + warpIn * 10;
        #pragma unroll
        for (int m = 0; m < MS; m++) {
            float Kv = ((m & 1) ? hi32(Kacc[m >> 1]) : lo32(Kacc[m >> 1])) + wkb;
            float s = warpsum(q * Kv);
            if (lane == 0) ap[m] = s;
        }
    }
    __syncthreads();

    // leaky-relu + softmax over m (one thread per head)
    if ((c & 63) == 0) {
        int h = c >> 6;
        const float* p0 = attn_p + wg * 40 + (2 * h) * 10;
        const float* p1 = p0 + 10;
        float a[MS];
        float mx = -1e30f;
        #pragma unroll
        for (int m = 0; m < MS; m++) {
            float x = p0[m] + p1[m];
            x = x > 0.f ? x : 0.2f * x;
            a[m] = x;
            mx = fmaxf(mx, x);
        }
        float se = 0.f;
        #pragma unroll
        for (int m = 0; m < MS; m++) { a[m] = expf(a[m] - mx); se += a[m]; }
        float inv = 1.f / se;
        float* awp = attn_w + wg * 20 + h * 10;
        #pragma unroll
        for (int m = 0; m < MS; m++) awp[m] = a[m] * inv;
    }
    __syncthreads();

    // weighted V + residual
    float o = memv;
    {
        const float* awp = attn_w + wg * 20 + (c >> 6) * 10;
        #pragma unroll
        for (int m = 0; m < MS; m++) {
            float Vv = ((m & 1) ? hi32(Vacc[m >> 1]) : lo32(Vacc[m >> 1])) + wvb;
            o = fmaf(awp[m], Vv, o);
        }
    }

    // layernorm across 128 (4 warps per node)
    {
        float s1 = warpsum(o);
        float s2 = warpsum(o * o);
        if (lane == 0) {
            red[wg * 8 + warpIn * 2]     = s1;
            red[wg * 8 + warpIn * 2 + 1] = s2;
        }
    }
    __syncthreads();
    {
        const float* rr = red + wg * 8;
        float mu  = (rr[0] + rr[2] + rr[4] + rr[6]) * (1.f / 128.f);
        float ms2 = (rr[1] + rr[3] + rr[5] + rr[7]) * (1.f / 128.f);
        float var = ms2 - mu * mu;
        float nv = (o - mu) * rsqrtf(var + EPSV) * ln_g[c] + ln_b[c];
        nrm_sm[wg * 128 + c] = nv;
    }
    __syncthreads();

    // MLP + relu -> mem_out
    {
        float acc = mlp_b[c];
        const float* nr = nrm_sm + wg * 128;
        #pragma unroll 4
        for (int j = 0; j < DIM; j++) acc = fmaf(nr[j], mlp_w[j * DIM + c], acc);
        out[(size_t)node_i * DIM + c] = fmaxf(acc, 0.f);
    }
}

// ---------------- kernel 2: link prediction heads ----------------
__global__ __launch_bounds__(128)
void k_link(const float* __restrict__ MO,
            const float* __restrict__ src_w, const float* __restrict__ src_b,
            const float* __restrict__ dst_w, const float* __restrict__ dst_b,
            const float* __restrict__ out_w, const float* __restrict__ out_b,
            float* __restrict__ pos, float* __restrict__ neg) {
    __shared__ float ssrc[128], sdst[128], sneg[128];
    __shared__ float red[8];
    const int i = blockIdx.x;
    const int c = threadIdx.x;
    const int lane = c & 31;
    const int w = c >> 5;

    ssrc[c] = MO[(size_t)i * 128 + c];
    sdst[c] = MO[(size_t)(BN + i) * 128 + c];
    sneg[c] = MO[(size_t)(2 * BN + i) * 128 + c];
    __syncthreads();

    float h = src_b[c], d = dst_b[c], n = dst_b[c];
    #pragma unroll 4
    for (int j = 0; j < 128; j++) {
        h = fmaf(ssrc[j], src_w[j * 128 + c], h);
        d = fmaf(sdst[j], dst_w[j * 128 + c], d);
        n = fmaf(sneg[j], dst_w[j * 128 + c], n);
    }
    float ow = out_w[c];
    float p = fmaxf(h + d, 0.f) * ow;
    float qn = fmaxf(h + n, 0.f) * ow;
    p = warpsum(p);
    qn = warpsum(qn);
    if (lane == 0) { red[w] = p; red[4 + w] = qn; }
    __syncthreads();
    if (c == 0) {
        float ob = out_b[0];
        pos[i] = red[0] + red[1] + red[2] + red[3] + ob;
        neg[i] = red[4] + red[5] + red[6] + red[7] + ob;
    }
}

// ---------------- kernel 3: segment scatter-add ----------------
__global__ __launch_bounds__(384)
void k_scatter(const float* __restrict__ MO, const float* __restrict__ efeat,
               const float* __restrict__ times,
               const int* __restrict__ dstindex, const int* __restrict__ src_seg,
               float* __restrict__ mail, float* __restrict__ ts) {
    const int e = blockIdx.x;
    const int c = threadIdx.x;   // 0..383
    const int r = dstindex[e];
    const int s = src_seg[e];
    float v;
    if (c < 128) {
        v = MO[(size_t)r * 128 + c];
    } else if (c < 256) {
        int r2 = (r < BN) ? (r + BN) : (r - BN);
        v = MO[(size_t)r2 * 128 + (c - 128)];
    } else {
        int rb = (r < BN) ? r : (r - BN);
        v = efeat[(size_t)rb * 128 + (c - 256)];
    }
    atomicAdd(mail + (size_t)s * DMSG + c, v);
    if (c == 0) {
        atomicAdd(&g_cnt[s], 1.0f);
        atomicAdd(ts + s, times[r]);
    }
}

// ---------------- kernel 4: per-segment reciprocal + ts scale ----------------
__global__ void k_inv(float* __restrict__ ts) {
    int i = blockIdx.x * blockDim.x + threadIdx.x;
    if (i < UU) {
        float inv = 1.0f / fmaxf(g_cnt[i], 1.0f);
        g_cnt[i] = inv;
        ts[i] *= inv;
    }
}

// ---------------- kernel 5: vectorized mail scale by reciprocal ----------------
__global__ void k_scale(float* __restrict__ mail) {
    unsigned i = blockIdx.x * blockDim.x + threadIdx.x;
    if (i < MAIL4) {
        float inv = g_cnt[i / (DMSG / 4)];   // 96 float4s per segment row
        float4 v = reinterpret_cast<float4*>(mail)[i];
        v.x *= inv; v.y *= inv; v.z *= inv; v.w *= inv;
        reinterpret_cast<float4*>(mail)[i] = v;
    }
}

// ---------------- launch ----------------
extern "C" void kernel_launch(void* const* d_in, const int* in_sizes, int n_in,
                              void* d_out, int out_size) {
    const int*   nodes      = (const int*)  d_in[0];
    const float* times      = (const float*)d_in[1];
    const float* mem_table  = (const float*)d_in[2];
    const float* mail_table = (const float*)d_in[3];
    const float* mail_time  = (const float*)d_in[4];
    const float* efeat      = (const float*)d_in[5];
    const float* wq_w = (const float*)d_in[6];
    const float* wq_b = (const float*)d_in[7];
    const float* wk_w = (const float*)d_in[8];
    const float* wk_b = (const float*)d_in[9];
    const float* wv_w = (const float*)d_in[10];
    const float* wv_b = (const float*)d_in[11];
    const float* mlp_w = (const float*)d_in[12];
    const float* mlp_b = (const float*)d_in[13];
    const float* ln_g  = (const float*)d_in[14];
    const float* ln_b  = (const float*)d_in[15];
    const float* te_w  = (const float*)d_in[16];
    const float* te_b  = (const float*)d_in[17];
    const float* src_w = (const float*)d_in[18];
    const float* src_b = (const float*)d_in[19];
    const float* dst_w = (const float*)d_in[20];
    const float* dst_b = (const float*)d_in[21];
    const float* out_w = (const float*)d_in[22];
    const float* out_b = (const float*)d_in[23];
    const int* dstindex = (const int*)d_in[24];
    const int* src_seg  = (const int*)d_in[25];

    float* out = (float*)d_out;

    cudaFuncSetAttribute(k_node, cudaFuncAttributeMaxDynamicSharedMemorySize, SM_BYTES);

    // 0) fused: interleave K/V weights + zero mail/ts/cnt (float4 stores)
    k_init<<<(MAIL4 + 2 * TS4 + 255) / 256, 256>>>(wk_w, wv_w, out);

    // 1) per-node attention + LN + MLP -> mem_out
    k_node<<<NN / G, 512, SM_BYTES>>>(
        nodes, times, mem_table, mail_table, mail_time,
        wq_w, wq_b, wk_b, wv_b, te_w, te_b,
        mlp_w, mlp_b, ln_g, ln_b, out);

    // 2) link prediction heads -> pos, neg
    k_link<<<BN, 128>>>(out, src_w, src_b, dst_w, dst_b, out_w, out_b,
                        out + OFF_POS, out + OFF_NEG);

    // 3) segment scatter-add
    k_scatter<<<EE, 384>>>(out, efeat, times, dstindex, src_seg,
                           out + OFF_MAIL, out + OFF_TS);

    // 4) per-segment reciprocal + ts scale
    k_inv<<<(UU + 255) / 256, 256>>>(out + OFF_TS);

    // 5) vectorized mail scale
    k_scale<<<(MAIL4 + 255) / 256, 256>>>(out + OFF_MAIL);
}